// round 4
// baseline (speedup 1.0000x reference)
#include <cuda_runtime.h>
#include <cuda_bf16.h>
#include <cstdint>

// d_in[0] = values     f32 [1048576, 8]
// d_in[1] = weights    f32 [65536, 8, 8]
// d_in[2] = input_idx  i32 [E]
// d_in[3] = weight_idx i32 [E]
// out     = f32 [E, 8]
//
// 8 lanes cooperate per edge; each thread handles 4 independent edges
// (g + j*E/4, j=0..3) to maximize loads in flight. Lane k loads W float4 #k
// and #(k+8) (full 128B line coverage); lane k loads x half (k&1) only.
// Pair shuffle combines halves; each lane owns one output element.

__device__ __forceinline__ float dot4(float4 a, float4 b) {
    float r = a.x * b.x;
    r = fmaf(a.y, b.y, r);
    r = fmaf(a.z, b.z, r);
    r = fmaf(a.w, b.w, r);
    return r;
}

__global__ __launch_bounds__(256, 4) void edge_mm_kernel(
    const float4* __restrict__ values,    // [NUM_VALUES*2]  float4
    const float4* __restrict__ weights,   // [NUM_WEIGHTS*16] float4
    const int*    __restrict__ input_idx,
    const int*    __restrict__ weight_idx,
    float*        __restrict__ out,
    int quarter_E)
{
    int tid = blockIdx.x * blockDim.x + threadIdx.x;
    int g = tid >> 3;           // edge-group id
    if (g >= quarter_E) return;
    int k = tid & 7;            // lane role within edge
    int half = k & 1;

    int vi[4], wi[4];
#pragma unroll
    for (int j = 0; j < 4; j++) {
        int e = g + j * quarter_E;
        vi[j] = __ldg(input_idx + e);
        wi[j] = __ldg(weight_idx + e);
    }

    // x halves: 16B per thread, reused by both W chunks
    float4 x[4];
#pragma unroll
    for (int j = 0; j < 4; j++)
        x[j] = values[vi[j] * 2 + half];

    // W quarter-rows: float4 #k = (row k>>1, cols half*4..), #(k+8) = row (k>>1)+4
    float4 w0[4], w1[4];
#pragma unroll
    for (int j = 0; j < 4; j++) {
        const float4* W = weights + wi[j] * 16;
        w0[j] = W[k];
        w1[j] = W[k + 8];
    }

    float y[4];
#pragma unroll
    for (int j = 0; j < 4; j++) {
        float p0 = dot4(w0[j], x[j]);
        float p1 = dot4(w1[j], x[j]);
        p0 += __shfl_xor_sync(0xFFFFFFFFu, p0, 1);
        p1 += __shfl_xor_sync(0xFFFFFFFFu, p1, 1);
        y[j] = half ? p1 : p0;
    }

    int pos = (k >> 1) + (half << 2);
#pragma unroll
    for (int j = 0; j < 4; j++) {
        int e = g + j * quarter_E;
        out[e * 8 + pos] = y[j];
    }
}

extern "C" void kernel_launch(void* const* d_in, const int* in_sizes, int n_in,
                              void* d_out, int out_size)
{
    const float4* values  = (const float4*)d_in[0];
    const float4* weights = (const float4*)d_in[1];
    const int* input_idx  = (const int*)d_in[2];
    const int* weight_idx = (const int*)d_in[3];
    float* out = (float*)d_out;

    int E = in_sizes[2];
    int quarter_E = E >> 2;            // E = 4194304, divisible by 4
    long long total = (long long)quarter_E * 8;
    int threads = 256;
    int blocks = (int)((total + threads - 1) / threads);

    edge_mm_kernel<<<blocks, threads>>>(values, weights, input_idx, weight_idx,
                                        out, quarter_E);
}

// round 5
// speedup vs baseline: 1.2713x; 1.2713x over previous
#include <cuda_runtime.h>
#include <cuda_bf16.h>
#include <cstdint>

// d_in[0] = values     f32 [1048576, 8]
// d_in[1] = weights    f32 [65536, 8, 8]
// d_in[2] = input_idx  i32 [E]
// d_in[3] = weight_idx i32 [E]
// out     = f32 [E, 8]
//
// 8 lanes cooperate per edge; 2 edge chains per iteration (e, e+E/2);
// persistent grid-stride loop with next-iteration index prefetch so the
// idx->gather dependency latency is hidden behind the current iteration's
// gather/compute phase.
// Lane k loads W float4 #k and #(k+8) (full 128B line coverage); lane k loads
// x half (k&1) only; shfl_xor(1) pair-sum; each lane owns one output element.

__device__ __forceinline__ float dot4(float4 a, float4 b) {
    float r = a.x * b.x;
    r = fmaf(a.y, b.y, r);
    r = fmaf(a.z, b.z, r);
    r = fmaf(a.w, b.w, r);
    return r;
}

__global__ __launch_bounds__(256) void edge_mm_kernel(
    const float4* __restrict__ values,    // [NUM_VALUES*2]  float4
    const float4* __restrict__ weights,   // [NUM_WEIGHTS*16] float4
    const int*    __restrict__ input_idx,
    const int*    __restrict__ weight_idx,
    float*        __restrict__ out,
    int half_E,
    int group_stride)                     // groups advanced per iteration
{
    int tid = blockIdx.x * blockDim.x + threadIdx.x;
    int g = tid >> 3;                     // edge-group id
    int k = tid & 7;                      // lane role within edge
    int half = k & 1;
    int pos = (k >> 1) + (half << 2);

    if (g >= half_E) return;

    // Prologue: load indices for the first group
    int vi0 = __ldg(input_idx + g);
    int wi0 = __ldg(weight_idx + g);
    int vi1 = __ldg(input_idx + g + half_E);
    int wi1 = __ldg(weight_idx + g + half_E);

    while (true) {
        int gn = g + group_stride;
        bool more = (gn < half_E);

        // Issue current gathers (dependent on already-resolved idx)
        float4 xa = values[vi0 * 2 + half];
        float4 xb = values[vi1 * 2 + half];
        const float4* W0 = weights + wi0 * 16;
        const float4* W1 = weights + wi1 * 16;
        float4 wa0 = W0[k];
        float4 wa1 = W0[k + 8];
        float4 wb0 = W1[k];
        float4 wb1 = W1[k + 8];

        // Prefetch next iteration's indices — overlaps with gather latency
        int nvi0 = 0, nwi0 = 0, nvi1 = 0, nwi1 = 0;
        if (more) {
            nvi0 = __ldg(input_idx + gn);
            nwi0 = __ldg(weight_idx + gn);
            nvi1 = __ldg(input_idx + gn + half_E);
            nwi1 = __ldg(weight_idx + gn + half_E);
        }

        // Compute
        float pa0 = dot4(wa0, xa);
        float pa1 = dot4(wa1, xa);
        float pb0 = dot4(wb0, xb);
        float pb1 = dot4(wb1, xb);

        pa0 += __shfl_xor_sync(0xFFFFFFFFu, pa0, 1);
        pa1 += __shfl_xor_sync(0xFFFFFFFFu, pa1, 1);
        pb0 += __shfl_xor_sync(0xFFFFFFFFu, pb0, 1);
        pb1 += __shfl_xor_sync(0xFFFFFFFFu, pb1, 1);

        float ya = half ? pa1 : pa0;
        float yb = half ? pb1 : pb0;

        out[g * 8 + pos] = ya;
        out[(g + half_E) * 8 + pos] = yb;

        if (!more) break;
        g = gn;
        vi0 = nvi0; wi0 = nwi0; vi1 = nvi1; wi1 = nwi1;
    }
}

extern "C" void kernel_launch(void* const* d_in, const int* in_sizes, int n_in,
                              void* d_out, int out_size)
{
    const float4* values  = (const float4*)d_in[0];
    const float4* weights = (const float4*)d_in[1];
    const int* input_idx  = (const int*)d_in[2];
    const int* weight_idx = (const int*)d_in[3];
    float* out = (float*)d_out;

    int E = in_sizes[2];
    int half_E = E >> 1;                  // E even (4194304)

    int threads = 256;
    int blocks = 2048;                    // persistent-ish: ~13-14 CTAs/SM waves
    int groups_per_iter = blocks * (threads >> 3);   // 65536
    // Cap blocks if problem is tiny
    long long total_groups = half_E;
    long long needed_blocks = (total_groups * 8 + threads - 1) / threads;
    if (needed_blocks < blocks) {
        blocks = (int)needed_blocks;
        groups_per_iter = blocks * (threads >> 3);
    }

    edge_mm_kernel<<<blocks, threads>>>(values, weights, input_idx, weight_idx,
                                        out, half_E, groups_per_iter);
}